// round 13
// baseline (speedup 1.0000x reference)
#include <cuda_runtime.h>
#include <cuda_fp16.h>
#include <cstdint>

#define NPIX 4096
#define CIN  256
#define CQK  64
#define BATCH 4
#define NCH  (NPIX / 64)

// ------------------------- device scratch ----------------------------------
__device__ float  g_w2[CIN * CIN];
__device__ __half g_wc[384 * CIN];
__device__ float  g_bc[384];
__device__ __half g_q[(size_t)BATCH * NPIX * CQK];   // [b][n][o]
__device__ __half g_k[(size_t)BATCH * NPIX * CQK];   // [b][m][o]
__device__ __half g_v[(size_t)BATCH * CIN * NPIX];   // [b][c][n]

// ------------------------- helpers -----------------------------------------
__device__ __forceinline__ uint32_t smem_u32(const void* p) {
    uint32_t a;
    asm("{ .reg .u64 t; cvta.to.shared.u64 t, %1; cvt.u32.u64 %0, t; }" : "=r"(a) : "l"(p));
    return a;
}
__device__ __forceinline__ void ldsm_x4(uint32_t a[4], uint32_t addr) {
    asm volatile("ldmatrix.sync.aligned.m8n8.x4.shared.b16 {%0,%1,%2,%3}, [%4];"
                 : "=r"(a[0]), "=r"(a[1]), "=r"(a[2]), "=r"(a[3]) : "r"(addr));
}
__device__ __forceinline__ void ldsm_x2(uint32_t a[2], uint32_t addr) {
    asm volatile("ldmatrix.sync.aligned.m8n8.x2.shared.b16 {%0,%1}, [%2];"
                 : "=r"(a[0]), "=r"(a[1]) : "r"(addr));
}
__device__ __forceinline__ void ldsm_x4_t(uint32_t a[4], uint32_t addr) {
    asm volatile("ldmatrix.sync.aligned.m8n8.x4.trans.shared.b16 {%0,%1,%2,%3}, [%4];"
                 : "=r"(a[0]), "=r"(a[1]), "=r"(a[2]), "=r"(a[3]) : "r"(addr));
}
__device__ __forceinline__ void ldsm_x2_t(uint32_t a[2], uint32_t addr) {
    asm volatile("ldmatrix.sync.aligned.m8n8.x2.trans.shared.b16 {%0,%1}, [%2];"
                 : "=r"(a[0]), "=r"(a[1]) : "r"(addr));
}
__device__ __forceinline__ void mma16816(float d[4], const uint32_t a[4], const uint32_t* b) {
    asm volatile(
        "mma.sync.aligned.m16n8k16.row.col.f32.f16.f16.f32 "
        "{%0,%1,%2,%3}, {%4,%5,%6,%7}, {%8,%9}, {%0,%1,%2,%3};"
        : "+f"(d[0]), "+f"(d[1]), "+f"(d[2]), "+f"(d[3])
        : "r"(a[0]), "r"(a[1]), "r"(a[2]), "r"(a[3]), "r"(b[0]), "r"(b[1]));
}
// fp16-accumulate variant: D fragment = 2 b32 regs of packed half2
__device__ __forceinline__ void mma16816_h(uint32_t d[2], const uint32_t a[4], const uint32_t* b) {
    asm volatile(
        "mma.sync.aligned.m16n8k16.row.col.f16.f16.f16.f16 "
        "{%0,%1}, {%2,%3,%4,%5}, {%6,%7}, {%0,%1};"
        : "+r"(d[0]), "+r"(d[1])
        : "r"(a[0]), "r"(a[1]), "r"(a[2]), "r"(a[3]), "r"(b[0]), "r"(b[1]));
}
#define CP_ASYNC16(dst, src) \
    asm volatile("cp.async.cg.shared.global [%0], [%1], 16;" :: "r"(dst), "l"(src))
#define CP_COMMIT() asm volatile("cp.async.commit_group;" ::: "memory")
#define CP_WAIT(n)  asm volatile("cp.async.wait_group %0;" :: "n"(n) : "memory")

__device__ __forceinline__ unsigned pk2(float a, float b) {
    __half2 h = __floats2half2_rn(a, b);
    return *(unsigned*)&h;
}
// elu on an already-packed half2: x>0 ? x : exp(x)-1
__device__ __forceinline__ unsigned elu2h(unsigned hu) {
    __half2 h = *(__half2*)&hu;
    __half2 hl = __hmul2(h, __float2half2_rn(1.44269504f));
    unsigned eu;
    asm("ex2.approx.f16x2 %0, %1;" : "=r"(eu) : "r"(*(unsigned*)&hl));
    __half2 em1 = __hsub2(*(__half2*)&eu, __float2half2_rn(1.0f));
    __half2 mask = __hgt2(h, __float2half2_rn(0.0f));
    __half2 r = __hfma2(mask, __hsub2(h, em1), em1);
    return *(unsigned*)&r;
}

// ------------------------- weight folding / packing ------------------------
__global__ void fold_w(const float* __restrict__ wg, const float* __restrict__ wv,
                       float* __restrict__ w2) {
    int o = blockIdx.x, j = threadIdx.x;
    float s = 0.f;
    for (int c = 0; c < CIN; c++) s += wg[o * CIN + c] * wv[c * CIN + j];
    w2[o * CIN + j] = s;
}
__global__ void pack_weights(const float* __restrict__ wq, const float* __restrict__ wk,
                             const float* __restrict__ w2, const float* __restrict__ bq,
                             const float* __restrict__ bk, const float* __restrict__ wg,
                             const float* __restrict__ bv, __half* __restrict__ Wc,
                             float* __restrict__ bc) {
    int r = blockIdx.x, c = threadIdx.x;
    const float* src = r < 64 ? wq + r * CIN : (r < 128 ? wk + (r - 64) * CIN : w2 + (r - 128) * CIN);
    Wc[r * CIN + c] = __float2half(src[c]);
    if (c == 0) {
        if (r < 64) bc[r] = bq[r];
        else if (r < 128) bc[r] = bk[r - 64];
        else {
            float s = 0.f;
            int o = r - 128;
            for (int cc = 0; cc < CIN; cc++) s += wg[o * CIN + cc] * bv[cc];
            bc[r] = s;
        }
    }
}

// ----------------- fused QKV projection (HMMA, fp16) -----------------------
#define XST 136
#define WST 72

__global__ __launch_bounds__(256) void proj_qkv(
    const float* __restrict__ X, const __half* __restrict__ Wc,
    const float* __restrict__ bc, __half* __restrict__ qout,
    __half* __restrict__ kout, __half* __restrict__ vout) {
    __shared__ __align__(16) __half XT[64 * XST];
    __shared__ __align__(16) __half WT[128 * WST];
    const int tid = threadIdx.x, lane = tid & 31, w = tid >> 5;
    const int wtile = blockIdx.x, n0 = blockIdx.y * 128, b = blockIdx.z;
    const float* Xb = X + (size_t)b * CIN * NPIX;
    const __half* Wrow = Wc + (size_t)wtile * 128 * CIN;

    const int wa = (w >> 2) * 64, wb = (w & 3) * 32;
    const uint32_t XTb = smem_u32(XT), WTb = smem_u32(WT);
    float d[4][4][4] = {};

    for (int ck = 0; ck < 4; ck++) {
        const int c0 = ck * 64;
#pragma unroll
        for (int it = 0; it < 8; it++) {
            int idx = it * 256 + tid;
            int cc = idx >> 5, ng = idx & 31;
            float4 x4 = *(const float4*)&Xb[(size_t)(c0 + cc) * NPIX + n0 + ng * 4];
            uint2 u;
            u.x = pk2(x4.x, x4.y);
            u.y = pk2(x4.z, x4.w);
            *(uint2*)&XT[cc * XST + ng * 4] = u;
        }
#pragma unroll
        for (int it = 0; it < 4; it++) {
            int idx = it * 256 + tid;
            int r = idx >> 3, g = idx & 7;
            *(uint4*)&WT[r * WST + g * 8] = *(const uint4*)&Wrow[(size_t)r * CIN + c0 + g * 8];
        }
        __syncthreads();

        if (wtile == 0) {
#pragma unroll
            for (int kk = 0; kk < 4; kk++) {
                const int kofs = kk * 16;
                uint32_t a[4][4], bb[4][2];
#pragma unroll
                for (int i = 0; i < 4; i++) {
                    int rc = kofs + (lane & 7) + (lane >> 4) * 8;
                    int cn = wa + i * 16 + ((lane >> 3) & 1) * 8;
                    ldsm_x4_t(a[i], XTb + (rc * XST + cn) * 2);
                }
#pragma unroll
                for (int j = 0; j < 4; j++) {
                    int l = lane & 15;
                    int row = wb + j * 8 + (l & 7);
                    int col = kofs + (l >> 3) * 8;
                    ldsm_x2(bb[j], WTb + (row * WST + col) * 2);
                }
#pragma unroll
                for (int i = 0; i < 4; i++)
#pragma unroll
                    for (int j = 0; j < 4; j++) mma16816(d[i][j], a[i], bb[j]);
            }
        } else {
#pragma unroll
            for (int kk = 0; kk < 4; kk++) {
                const int kofs = kk * 16;
                uint32_t a[4][4], bb[4][2];
#pragma unroll
                for (int i = 0; i < 4; i++) {
                    int row = wa + i * 16 + (lane & 7) + ((lane >> 3) & 1) * 8;
                    int col = kofs + (lane >> 4) * 8;
                    ldsm_x4(a[i], WTb + (row * WST + col) * 2);
                }
#pragma unroll
                for (int j = 0; j < 4; j++) {
                    int l = lane & 15;
                    int rc = kofs + l;
                    int cn = wb + j * 8;
                    ldsm_x2_t(bb[j], XTb + (rc * XST + cn) * 2);
                }
#pragma unroll
                for (int i = 0; i < 4; i++)
#pragma unroll
                    for (int j = 0; j < 4; j++) mma16816(d[i][j], a[i], bb[j]);
            }
        }
        __syncthreads();
    }

    if (wtile == 0) {
#pragma unroll
        for (int j = 0; j < 4; j++) {
            int o = wb + j * 8 + (lane & 3) * 2;
            float b0 = bc[o], b1 = bc[o + 1];
            __half* dst = o < 64 ? qout : kout;
            int oo = o < 64 ? o : o - 64;
#pragma unroll
            for (int i = 0; i < 4; i++) {
                int n = n0 + wa + i * 16 + (lane >> 2);
                float* dd = d[i][j];
                *(unsigned*)&dst[((size_t)b * NPIX + n) * CQK + oo] = pk2(dd[0] + b0, dd[1] + b1);
                *(unsigned*)&dst[((size_t)b * NPIX + n + 8) * CQK + oo] = pk2(dd[2] + b0, dd[3] + b1);
            }
        }
    } else {
#pragma unroll
        for (int i = 0; i < 4; i++) {
            int c = (wtile - 1) * 128 + wa + i * 16 + (lane >> 2);
            float b0 = bc[128 + c], b1 = bc[128 + c + 8];
#pragma unroll
            for (int j = 0; j < 4; j++) {
                int n = n0 + wb + j * 8 + (lane & 3) * 2;
                float* dd = d[i][j];
                *(unsigned*)&vout[((size_t)b * CIN + c) * NPIX + n] = pk2(dd[0] + b0, dd[1] + b0);
                *(unsigned*)&vout[((size_t)b * CIN + c + 8) * NPIX + n] = pk2(dd[2] + b1, dd[3] + b1);
            }
        }
    }
}

// ------ fused attention: warp-specialized pipelined energy + AV ------------
// CTA = (m-tile 128, batch), 384 thr. Warps 0-7: AV (64c x 64m each);
// warps 8-11: energy (32m x 64n each, k register-resident, fp16-acc MMA).
// Per chunk: one __syncthreads; AV(ch) reads E[ch&1] while energy writes E[(ch+1)&1].
#define FST 72   // k, q stride (halves)
#define EST 72   // E stride (halves)
#define K_OFF 0                           // 128*72 = 9216
#define E_OFF(p) (9216 + (p) * 9216)      // 2 x 128*72
#define Q_OFF(i) (27648 + (i) * 4608)     // 3 x 64*72
#define V_OFF(i) (41472 + (i) * 16384)    // 3 x 256*64 (swizzled)
#define TOT_H 90624                       // halves = 181248 B

__global__ __launch_bounds__(384, 1) void fused_attn(
    const __half* __restrict__ qg, const __half* __restrict__ kg,
    const __half* __restrict__ vg, const float* __restrict__ bgb,
    float* __restrict__ out) {
    extern __shared__ __half sm[];
    const int tid = threadIdx.x, lane = tid & 31, w = tid >> 5;
    const int m0 = blockIdx.x * 128, b = blockIdx.y;
    const uint32_t smb = smem_u32(sm);

    const __half* qgb = qg + (size_t)b * NPIX * CQK;
    const __half* vgb = vg + (size_t)b * CIN * NPIX;

    // ---- prologue: k (tid<256) + q(0) (tid>=256) direct loads
    if (tid < 256) {
        const uint4* kg4 = (const uint4*)(kg + ((size_t)b * NPIX + m0) * CQK);
#pragma unroll
        for (int it = 0; it < 4; it++) {
            int idx = tid + 256 * it;
            int r = idx >> 3, s = idx & 7;
            *(uint4*)&sm[K_OFF + r * FST + s * 8] = kg4[idx];
        }
    } else {
        const uint4* qg4 = (const uint4*)qgb;
        int t = tid - 256;
#pragma unroll
        for (int it = 0; it < 4; it++) {
            int idx = t + 128 * it;
            int r = idx >> 3, s = idx & 7;
            *(uint4*)&sm[Q_OFF(0) + r * FST + s * 8] = qg4[idx];
        }
    }

    // group i: v(i) -> V(i%3) [if valid], q(i+1) -> Q((i+1)%3) [if valid].
    // ALWAYS commits exactly one group.
    auto prefetch = [&](int i) {
        if (tid < 256) {
            if (i < NCH) {
                const int n0 = i * 64;
                const uint32_t vdst = smb + V_OFF(i % 3) * 2;
#pragma unroll
                for (int it = 0; it < 8; it++) {
                    int idx = tid + 256 * it;
                    int r = idx >> 3, s = idx & 7;
                    CP_ASYNC16(vdst + (r * 64 + ((s ^ (r & 7)) * 8)) * 2,
                               vgb + (size_t)r * NPIX + n0 + s * 8);
                }
            }
        } else if (i + 1 < NCH) {
            const uint32_t qdst = smb + Q_OFF((i + 1) % 3) * 2;
            int t = tid - 256;
#pragma unroll
            for (int it = 0; it < 4; it++) {
                int idx = t + 128 * it;
                int r = idx >> 3, s = idx & 7;
                CP_ASYNC16(qdst + (r * FST + s * 8) * 2,
                           qgb + (size_t)((i + 1) * 64 + r) * CQK + s * 8);
            }
        }
        CP_COMMIT();
    };

    prefetch(0);
    prefetch(1);
    __syncthreads();  // k, q(0) visible

    const uint32_t ksb = smb + K_OFF * 2;

    if (w >= 8) {
        // =================== ENERGY WARPS (4), fp16-acc MMA ===================
        const int ew = w - 8;
        const int wme = ew * 32;

        uint32_t kfr[4][2][4];
#pragma unroll
        for (int kk = 0; kk < 4; kk++)
#pragma unroll
            for (int i = 0; i < 2; i++) {
                int row = wme + i * 16 + (lane & 7) + ((lane >> 3) & 1) * 8;
                int col = kk * 16 + (lane >> 4) * 8;
                ldsm_x4(kfr[kk][i], ksb + (row * FST + col) * 2);
            }

        auto energy = [&](int en) {
            const uint32_t qsb = smb + Q_OFF(en % 3) * 2;
            const uint32_t edst = smb + E_OFF(en & 1) * 2;
            uint32_t de[2][8][2] = {};  // packed half2 accumulators (zero = +0.0h)
#pragma unroll
            for (int kk = 0; kk < 4; kk++) {
                const int ko = kk * 16;
#pragma unroll
                for (int jj = 0; jj < 4; jj++) {
                    uint32_t b4[4];
                    int row = jj * 16 + (lane & 7) + (lane >> 4) * 8;
                    int col = ko + ((lane >> 3) & 1) * 8;
                    ldsm_x4(b4, qsb + (row * FST + col) * 2);
#pragma unroll
                    for (int i = 0; i < 2; i++) {
                        mma16816_h(de[i][2 * jj], kfr[kk][i], b4);
                        mma16816_h(de[i][2 * jj + 1], kfr[kk][i], b4 + 2);
                    }
                }
            }
            const int m = wme + (lane >> 2);
            const int nb = (lane & 3) * 2;
#pragma unroll
            for (int i = 0; i < 2; i++)
#pragma unroll
                for (int j = 0; j < 8; j++) {
                    int col = nb + j * 8;
                    asm volatile("st.shared.u32 [%0], %1;" ::
                                 "r"(edst + ((m + i * 16) * EST + col) * 2),
                                 "r"(elu2h(de[i][j][0])));
                    asm volatile("st.shared.u32 [%0], %1;" ::
                                 "r"(edst + ((m + i * 16 + 8) * EST + col) * 2),
                                 "r"(elu2h(de[i][j][1])));
                }
        };

        energy(0);  // prologue: E[0]

        for (int ch = 0; ch < NCH; ch++) {
            if (ch >= NCH - 1) CP_WAIT(0); else CP_WAIT(1);
            __syncthreads();
            prefetch(ch + 2);
            if (ch + 1 < NCH) energy(ch + 1);
        }
    } else {
        // =================== AV WARPS (8), fp32 acc ===================
        const int wc = (w >> 1) * 64, wm = (w & 1) * 64;
        float acc[4][8][4] = {};

        for (int ch = 0; ch < NCH; ch++) {
            if (ch >= NCH - 1) CP_WAIT(0); else CP_WAIT(1);
            __syncthreads();
            prefetch(ch + 2);

            const uint32_t vsb = smb + V_OFF(ch % 3) * 2;
            const uint32_t esb = smb + E_OFF(ch & 1) * 2;
#pragma unroll
            for (int kk = 0; kk < 4; kk++) {
                const int ko = kk * 16;
                uint32_t a[4][4];
#pragma unroll
                for (int i = 0; i < 4; i++) {
                    int row = wc + i * 16 + (lane & 7) + ((lane >> 3) & 1) * 8;
                    int cnk = (ko >> 3) + (lane >> 4);
                    ldsm_x4(a[i], vsb + (row * 64 + ((cnk ^ (row & 7)) * 8)) * 2);
                }
#pragma unroll
                for (int jj = 0; jj < 4; jj++) {
                    uint32_t b4[4];
                    int row = wm + jj * 16 + (lane & 7) + (lane >> 4) * 8;
                    int col = ko + ((lane >> 3) & 1) * 8;
                    ldsm_x4(b4, esb + (row * EST + col) * 2);
#pragma unroll
                    for (int i = 0; i < 4; i++) {
                        mma16816(acc[i][2 * jj], a[i], b4);
                        mma16816(acc[i][2 * jj + 1], a[i], b4 + 2);
                    }
                }
            }
        }

        // ---- epilogue: /N + bias (AV warps only)
        const float scale = 1.0f / (float)NPIX;
#pragma unroll
        for (int i = 0; i < 4; i++) {
            int c = wc + i * 16 + (lane >> 2);
            float b0 = bgb[c], b1 = bgb[c + 8];
#pragma unroll
            for (int j = 0; j < 8; j++) {
                int m = m0 + wm + j * 8 + (lane & 3) * 2;
                float* dd = acc[i][j];
                *(float2*)&out[((size_t)b * CIN + c) * NPIX + m] =
                    make_float2(dd[0] * scale + b0, dd[1] * scale + b0);
                *(float2*)&out[((size_t)b * CIN + c + 8) * NPIX + m] =
                    make_float2(dd[2] * scale + b1, dd[3] * scale + b1);
            }
        }
    }
}

// ------------------------------- launch -------------------------------------
extern "C" void kernel_launch(void* const* d_in, const int* in_sizes, int n_in,
                              void* d_out, int out_size) {
    const float* x  = (const float*)d_in[0];
    const float* wq = (const float*)d_in[1];
    const float* bq = (const float*)d_in[2];
    const float* wk = (const float*)d_in[3];
    const float* bk = (const float*)d_in[4];
    const float* wv = (const float*)d_in[5];
    const float* bv = (const float*)d_in[6];
    const float* wg = (const float*)d_in[7];
    const float* bg = (const float*)d_in[8];
    float* out = (float*)d_out;

    float *w2p, *bcp;
    __half *wcp, *qp, *kp, *vp;
    cudaGetSymbolAddress((void**)&w2p, g_w2);
    cudaGetSymbolAddress((void**)&wcp, g_wc);
    cudaGetSymbolAddress((void**)&bcp, g_bc);
    cudaGetSymbolAddress((void**)&qp, g_q);
    cudaGetSymbolAddress((void**)&kp, g_k);
    cudaGetSymbolAddress((void**)&vp, g_v);

    const int F_SMEM = TOT_H * (int)sizeof(__half);  // 181248
    cudaFuncSetAttribute(fused_attn, cudaFuncAttributeMaxDynamicSharedMemorySize, F_SMEM);

    fold_w<<<CIN, CIN>>>(wg, wv, w2p);
    pack_weights<<<384, CIN>>>(wq, wk, w2p, bq, bk, wg, bv, wcp, bcp);

    proj_qkv<<<dim3(3, NPIX / 128, BATCH), 256>>>(x, wcp, bcp, qp, kp, vp);

    fused_attn<<<dim3(NPIX / 128, BATCH), 384, F_SMEM>>>(qp, kp, vp, bg, out);
}

// round 14
// speedup vs baseline: 1.0675x; 1.0675x over previous
#include <cuda_runtime.h>
#include <cuda_fp16.h>
#include <cstdint>

#define NPIX 4096
#define CIN  256
#define CQK  64
#define BATCH 4
#define NCH  (NPIX / 64)

// ------------------------- device scratch ----------------------------------
__device__ float  g_w2[CIN * CIN];
__device__ __half g_wc[384 * CIN];
__device__ float  g_bc[384];
__device__ __half g_q[(size_t)BATCH * NPIX * CQK];   // [b][n][o]
__device__ __half g_k[(size_t)BATCH * NPIX * CQK];   // [b][m][o]
__device__ __half g_v[(size_t)BATCH * CIN * NPIX];   // [b][c][n]

// ------------------------- helpers -----------------------------------------
__device__ __forceinline__ uint32_t smem_u32(const void* p) {
    uint32_t a;
    asm("{ .reg .u64 t; cvta.to.shared.u64 t, %1; cvt.u32.u64 %0, t; }" : "=r"(a) : "l"(p));
    return a;
}
__device__ __forceinline__ void ldsm_x4(uint32_t a[4], uint32_t addr) {
    asm volatile("ldmatrix.sync.aligned.m8n8.x4.shared.b16 {%0,%1,%2,%3}, [%4];"
                 : "=r"(a[0]), "=r"(a[1]), "=r"(a[2]), "=r"(a[3]) : "r"(addr));
}
__device__ __forceinline__ void ldsm_x2(uint32_t a[2], uint32_t addr) {
    asm volatile("ldmatrix.sync.aligned.m8n8.x2.shared.b16 {%0,%1}, [%2];"
                 : "=r"(a[0]), "=r"(a[1]) : "r"(addr));
}
__device__ __forceinline__ void ldsm_x4_t(uint32_t a[4], uint32_t addr) {
    asm volatile("ldmatrix.sync.aligned.m8n8.x4.trans.shared.b16 {%0,%1,%2,%3}, [%4];"
                 : "=r"(a[0]), "=r"(a[1]), "=r"(a[2]), "=r"(a[3]) : "r"(addr));
}
__device__ __forceinline__ void ldsm_x2_t(uint32_t a[2], uint32_t addr) {
    asm volatile("ldmatrix.sync.aligned.m8n8.x2.trans.shared.b16 {%0,%1}, [%2];"
                 : "=r"(a[0]), "=r"(a[1]) : "r"(addr));
}
__device__ __forceinline__ void mma16816(float d[4], const uint32_t a[4], const uint32_t* b) {
    asm volatile(
        "mma.sync.aligned.m16n8k16.row.col.f32.f16.f16.f32 "
        "{%0,%1,%2,%3}, {%4,%5,%6,%7}, {%8,%9}, {%0,%1,%2,%3};"
        : "+f"(d[0]), "+f"(d[1]), "+f"(d[2]), "+f"(d[3])
        : "r"(a[0]), "r"(a[1]), "r"(a[2]), "r"(a[3]), "r"(b[0]), "r"(b[1]));
}
#define CP_ASYNC16(dst, src) \
    asm volatile("cp.async.cg.shared.global [%0], [%1], 16;" :: "r"(dst), "l"(src))
#define CP_COMMIT() asm volatile("cp.async.commit_group;" ::: "memory")
#define CP_WAIT(n)  asm volatile("cp.async.wait_group %0;" :: "n"(n) : "memory")
#define BAR_SYNC(id, cnt)   asm volatile("bar.sync %0, %1;" :: "r"(id), "r"(cnt) : "memory")
#define BAR_ARRIVE(id, cnt) asm volatile("bar.arrive %0, %1;" :: "r"(id), "r"(cnt) : "memory")
#define MEMBAR_CTA() asm volatile("membar.cta;" ::: "memory")

// named barrier ids (0 reserved for __syncthreads)
#define FULL_BAR(p)  (1 + (p))   // energy arrives(128), AV syncs(256); count 384
#define EMPTY_BAR(p) (3 + (p))   // AV arrives(256), energy syncs(128); count 384
#define EN_BAR 5                 // energy-group local, count 128
#define AV_BAR 6                 // AV-group local, count 256

__device__ __forceinline__ unsigned pk2(float a, float b) {
    __half2 h = __floats2half2_rn(a, b);
    return *(unsigned*)&h;
}
// elu on a packed fp16x2 pair built from two floats
__device__ __forceinline__ unsigned elu2(float x0, float x1) {
    __half2 h = __floats2half2_rn(x0, x1);
    __half2 hl = __hmul2(h, __float2half2_rn(1.44269504f));
    unsigned eu;
    asm("ex2.approx.f16x2 %0, %1;" : "=r"(eu) : "r"(*(unsigned*)&hl));
    __half2 em1 = __hsub2(*(__half2*)&eu, __float2half2_rn(1.0f));
    __half2 mask = __hgt2(h, __float2half2_rn(0.0f));
    __half2 r = __hfma2(mask, __hsub2(h, em1), em1);
    return *(unsigned*)&r;
}

// ------------------------- weight folding / packing ------------------------
__global__ void fold_w(const float* __restrict__ wg, const float* __restrict__ wv,
                       float* __restrict__ w2) {
    int o = blockIdx.x, j = threadIdx.x;
    float s = 0.f;
    for (int c = 0; c < CIN; c++) s += wg[o * CIN + c] * wv[c * CIN + j];
    w2[o * CIN + j] = s;
}
__global__ void pack_weights(const float* __restrict__ wq, const float* __restrict__ wk,
                             const float* __restrict__ w2, const float* __restrict__ bq,
                             const float* __restrict__ bk, const float* __restrict__ wg,
                             const float* __restrict__ bv, __half* __restrict__ Wc,
                             float* __restrict__ bc) {
    int r = blockIdx.x, c = threadIdx.x;
    const float* src = r < 64 ? wq + r * CIN : (r < 128 ? wk + (r - 64) * CIN : w2 + (r - 128) * CIN);
    Wc[r * CIN + c] = __float2half(src[c]);
    if (c == 0) {
        if (r < 64) bc[r] = bq[r];
        else if (r < 128) bc[r] = bk[r - 64];
        else {
            float s = 0.f;
            int o = r - 128;
            for (int cc = 0; cc < CIN; cc++) s += wg[o * CIN + cc] * bv[cc];
            bc[r] = s;
        }
    }
}

// ----------------- fused QKV projection (HMMA, fp16) -----------------------
#define XST 136
#define WST 72

__global__ __launch_bounds__(256) void proj_qkv(
    const float* __restrict__ X, const __half* __restrict__ Wc,
    const float* __restrict__ bc, __half* __restrict__ qout,
    __half* __restrict__ kout, __half* __restrict__ vout) {
    __shared__ __align__(16) __half XT[64 * XST];
    __shared__ __align__(16) __half WT[128 * WST];
    const int tid = threadIdx.x, lane = tid & 31, w = tid >> 5;
    const int wtile = blockIdx.x, n0 = blockIdx.y * 128, b = blockIdx.z;
    const float* Xb = X + (size_t)b * CIN * NPIX;
    const __half* Wrow = Wc + (size_t)wtile * 128 * CIN;

    const int wa = (w >> 2) * 64, wb = (w & 3) * 32;
    const uint32_t XTb = smem_u32(XT), WTb = smem_u32(WT);
    float d[4][4][4] = {};

    for (int ck = 0; ck < 4; ck++) {
        const int c0 = ck * 64;
#pragma unroll
        for (int it = 0; it < 8; it++) {
            int idx = it * 256 + tid;
            int cc = idx >> 5, ng = idx & 31;
            float4 x4 = *(const float4*)&Xb[(size_t)(c0 + cc) * NPIX + n0 + ng * 4];
            uint2 u;
            u.x = pk2(x4.x, x4.y);
            u.y = pk2(x4.z, x4.w);
            *(uint2*)&XT[cc * XST + ng * 4] = u;
        }
#pragma unroll
        for (int it = 0; it < 4; it++) {
            int idx = it * 256 + tid;
            int r = idx >> 3, g = idx & 7;
            *(uint4*)&WT[r * WST + g * 8] = *(const uint4*)&Wrow[(size_t)r * CIN + c0 + g * 8];
        }
        __syncthreads();

        if (wtile == 0) {
#pragma unroll
            for (int kk = 0; kk < 4; kk++) {
                const int kofs = kk * 16;
                uint32_t a[4][4], bb[4][2];
#pragma unroll
                for (int i = 0; i < 4; i++) {
                    int rc = kofs + (lane & 7) + (lane >> 4) * 8;
                    int cn = wa + i * 16 + ((lane >> 3) & 1) * 8;
                    ldsm_x4_t(a[i], XTb + (rc * XST + cn) * 2);
                }
#pragma unroll
                for (int j = 0; j < 4; j++) {
                    int l = lane & 15;
                    int row = wb + j * 8 + (l & 7);
                    int col = kofs + (l >> 3) * 8;
                    ldsm_x2(bb[j], WTb + (row * WST + col) * 2);
                }
#pragma unroll
                for (int i = 0; i < 4; i++)
#pragma unroll
                    for (int j = 0; j < 4; j++) mma16816(d[i][j], a[i], bb[j]);
            }
        } else {
#pragma unroll
            for (int kk = 0; kk < 4; kk++) {
                const int kofs = kk * 16;
                uint32_t a[4][4], bb[4][2];
#pragma unroll
                for (int i = 0; i < 4; i++) {
                    int row = wa + i * 16 + (lane & 7) + ((lane >> 3) & 1) * 8;
                    int col = kofs + (lane >> 4) * 8;
                    ldsm_x4(a[i], WTb + (row * WST + col) * 2);
                }
#pragma unroll
                for (int j = 0; j < 4; j++) {
                    int l = lane & 15;
                    int rc = kofs + l;
                    int cn = wb + j * 8;
                    ldsm_x2_t(bb[j], XTb + (rc * XST + cn) * 2);
                }
#pragma unroll
                for (int i = 0; i < 4; i++)
#pragma unroll
                    for (int j = 0; j < 4; j++) mma16816(d[i][j], a[i], bb[j]);
            }
        }
        __syncthreads();
    }

    if (wtile == 0) {
#pragma unroll
        for (int j = 0; j < 4; j++) {
            int o = wb + j * 8 + (lane & 3) * 2;
            float b0 = bc[o], b1 = bc[o + 1];
            __half* dst = o < 64 ? qout : kout;
            int oo = o < 64 ? o : o - 64;
#pragma unroll
            for (int i = 0; i < 4; i++) {
                int n = n0 + wa + i * 16 + (lane >> 2);
                float* dd = d[i][j];
                *(unsigned*)&dst[((size_t)b * NPIX + n) * CQK + oo] = pk2(dd[0] + b0, dd[1] + b1);
                *(unsigned*)&dst[((size_t)b * NPIX + n + 8) * CQK + oo] = pk2(dd[2] + b0, dd[3] + b1);
            }
        }
    } else {
#pragma unroll
        for (int i = 0; i < 4; i++) {
            int c = (wtile - 1) * 128 + wa + i * 16 + (lane >> 2);
            float b0 = bc[128 + c], b1 = bc[128 + c + 8];
#pragma unroll
            for (int j = 0; j < 4; j++) {
                int n = n0 + wb + j * 8 + (lane & 3) * 2;
                float* dd = d[i][j];
                *(unsigned*)&vout[((size_t)b * CIN + c) * NPIX + n] = pk2(dd[0] + b0, dd[1] + b0);
                *(unsigned*)&vout[((size_t)b * CIN + c + 8) * NPIX + n] = pk2(dd[2] + b1, dd[3] + b1);
            }
        }
    }
}

// ------ fused attention: decoupled producer/consumer warp groups -----------
// CTA = (m-tile 128, batch), 384 thr. Warps 0-7: AV consumers (64c x 64m);
// warps 8-11: energy producers (32m x 64n, k register-resident).
// E double-buffered, guarded by FULL/EMPTY named barriers (no __syncthreads
// in the main loop). Each group paces its own cp.async stream.
#define FST 72   // k, q stride (halves)
#define EST 72   // E stride (halves)
#define K_OFF 0                           // 128*72 = 9216
#define E_OFF(p) (9216 + (p) * 9216)      // 2 x 128*72
#define Q_OFF(i) (27648 + (i) * 4608)     // 3 x 64*72
#define V_OFF(i) (41472 + (i) * 16384)    // 3 x 256*64 (swizzled)
#define TOT_H 90624                       // halves = 181248 B

__global__ __launch_bounds__(384, 1) void fused_attn(
    const __half* __restrict__ qg, const __half* __restrict__ kg,
    const __half* __restrict__ vg, const float* __restrict__ bgb,
    float* __restrict__ out) {
    extern __shared__ __half sm[];
    const int tid = threadIdx.x, lane = tid & 31, w = tid >> 5;
    const int m0 = blockIdx.x * 128, b = blockIdx.y;
    const uint32_t smb = smem_u32(sm);

    const __half* qgb = qg + (size_t)b * NPIX * CQK;
    const __half* vgb = vg + (size_t)b * CIN * NPIX;

    // per-group prefetch: AV threads load v(i); energy threads load q(i+1).
    // Each call commits exactly one group on the calling thread.
    auto prefetch_v = [&](int i) {  // AV threads only (tid < 256)
        if (i < NCH) {
            const int n0 = i * 64;
            const uint32_t vdst = smb + V_OFF(i % 3) * 2;
#pragma unroll
            for (int it = 0; it < 8; it++) {
                int idx = tid + 256 * it;
                int r = idx >> 3, s = idx & 7;
                CP_ASYNC16(vdst + (r * 64 + ((s ^ (r & 7)) * 8)) * 2,
                           vgb + (size_t)r * NPIX + n0 + s * 8);
            }
        }
        CP_COMMIT();
    };
    auto prefetch_q = [&](int i) {  // energy threads only (tid >= 256); loads q(i)
        if (i < NCH) {
            const uint32_t qdst = smb + Q_OFF(i % 3) * 2;
            int t = tid - 256;
#pragma unroll
            for (int it = 0; it < 4; it++) {
                int idx = t + 128 * it;
                int r = idx >> 3, s = idx & 7;
                CP_ASYNC16(qdst + (r * FST + s * 8) * 2,
                           qgb + (size_t)(i * 64 + r) * CQK + s * 8);
            }
        }
        CP_COMMIT();
    };

    // ---- prologue: k (AV threads) + q(0) (energy threads) direct loads
    if (tid < 256) {
        const uint4* kg4 = (const uint4*)(kg + ((size_t)b * NPIX + m0) * CQK);
#pragma unroll
        for (int it = 0; it < 4; it++) {
            int idx = tid + 256 * it;
            int r = idx >> 3, s = idx & 7;
            *(uint4*)&sm[K_OFF + r * FST + s * 8] = kg4[idx];
        }
        prefetch_v(0);
        prefetch_v(1);
    } else {
        const uint4* qg4 = (const uint4*)qgb;
        int t = tid - 256;
#pragma unroll
        for (int it = 0; it < 4; it++) {
            int idx = t + 128 * it;
            int r = idx >> 3, s = idx & 7;
            *(uint4*)&sm[Q_OFF(0) + r * FST + s * 8] = qg4[idx];
        }
        prefetch_q(1);
        prefetch_q(2);
    }
    __syncthreads();  // k, q(0) visible to everyone

    const uint32_t ksb = smb + K_OFF * 2;

    if (w >= 8) {
        // =================== ENERGY PRODUCERS (4 warps) ===================
        const int ew = w - 8;
        const int wme = ew * 32;

        uint32_t kfr[4][2][4];
#pragma unroll
        for (int kk = 0; kk < 4; kk++)
#pragma unroll
            for (int i = 0; i < 2; i++) {
                int row = wme + i * 16 + (lane & 7) + ((lane >> 3) & 1) * 8;
                int col = kk * 16 + (lane >> 4) * 8;
                ldsm_x4(kfr[kk][i], ksb + (row * FST + col) * 2);
            }

        auto energy = [&](int en) {
            const uint32_t qsb = smb + Q_OFF(en % 3) * 2;
            const uint32_t edst = smb + E_OFF(en & 1) * 2;
            float de[2][8][4] = {};
#pragma unroll
            for (int kk = 0; kk < 4; kk++) {
                const int ko = kk * 16;
#pragma unroll
                for (int jj = 0; jj < 4; jj++) {
                    uint32_t b4[4];
                    int row = jj * 16 + (lane & 7) + (lane >> 4) * 8;
                    int col = ko + ((lane >> 3) & 1) * 8;
                    ldsm_x4(b4, qsb + (row * FST + col) * 2);
#pragma unroll
                    for (int i = 0; i < 2; i++) {
                        mma16816(de[i][2 * jj], kfr[kk][i], b4);
                        mma16816(de[i][2 * jj + 1], kfr[kk][i], b4 + 2);
                    }
                }
            }
            const int m = wme + (lane >> 2);
            const int nb = (lane & 3) * 2;
#pragma unroll
            for (int i = 0; i < 2; i++)
#pragma unroll
                for (int j = 0; j < 8; j++) {
                    int col = nb + j * 8;
                    float* dd = de[i][j];
                    asm volatile("st.shared.u32 [%0], %1;" ::
                                 "r"(edst + ((m + i * 16) * EST + col) * 2),
                                 "r"(elu2(dd[0], dd[1])));
                    asm volatile("st.shared.u32 [%0], %1;" ::
                                 "r"(edst + ((m + i * 16 + 8) * EST + col) * 2),
                                 "r"(elu2(dd[2], dd[3])));
                }
        };

        // en = 0: q(0) direct-loaded, E[0] free
        energy(0);
        MEMBAR_CTA();
        BAR_ARRIVE(FULL_BAR(0), 384);

        for (int en = 1; en < NCH; en++) {
            CP_WAIT(1);                   // q(en) group complete
            BAR_SYNC(EN_BAR, 128);        // visibility + all producers past en-1
            prefetch_q(en + 2);           // safe: q((en+2)%3) slot consumed at en-1
            if (en >= 2) BAR_SYNC(EMPTY_BAR(en & 1), 384);
            energy(en);
            MEMBAR_CTA();
            BAR_ARRIVE(FULL_BAR(en & 1), 384);
        }
    } else {
        // =================== AV CONSUMERS (8 warps) ===================
        const int wc = (w >> 1) * 64, wm = (w & 1) * 64;
        float acc[4][8][4] = {};

        for (int ch = 0; ch < NCH; ch++) {
            CP_WAIT(1);                   // v(ch) group complete
            BAR_SYNC(AV_BAR, 256);        // visibility + all consumers past ch-1
            prefetch_v(ch + 2);           // safe: v((ch+2)%3) slot consumed at ch-1
            BAR_SYNC(FULL_BAR(ch & 1), 384);  // E[ch&1] produced

            const uint32_t vsb = smb + V_OFF(ch % 3) * 2;
            const uint32_t esb = smb + E_OFF(ch & 1) * 2;
#pragma unroll
            for (int kk = 0; kk < 4; kk++) {
                const int ko = kk * 16;
                uint32_t a[4][4];
#pragma unroll
                for (int i = 0; i < 4; i++) {
                    int row = wc + i * 16 + (lane & 7) + ((lane >> 3) & 1) * 8;
                    int cnk = (ko >> 3) + (lane >> 4);
                    ldsm_x4(a[i], vsb + (row * 64 + ((cnk ^ (row & 7)) * 8)) * 2);
                }
#pragma unroll
                for (int jj = 0; jj < 4; jj++) {
                    uint32_t b4[4];
                    int row = wm + jj * 16 + (lane & 7) + (lane >> 4) * 8;
                    int col = ko + ((lane >> 3) & 1) * 8;
                    ldsm_x4(b4, esb + (row * EST + col) * 2);
#pragma unroll
                    for (int i = 0; i < 4; i++) {
                        mma16816(acc[i][2 * jj], a[i], b4);
                        mma16816(acc[i][2 * jj + 1], a[i], b4 + 2);
                    }
                }
            }
            BAR_ARRIVE(EMPTY_BAR(ch & 1), 384);  // E[ch&1] free for reuse
        }

        // ---- epilogue: /N + bias (AV warps only)
        const float scale = 1.0f / (float)NPIX;
#pragma unroll
        for (int i = 0; i < 4; i++) {
            int c = wc + i * 16 + (lane >> 2);
            float b0 = bgb[c], b1 = bgb[c + 8];
#pragma unroll
            for (int j = 0; j < 8; j++) {
                int m = m0 + wm + j * 8 + (lane & 3) * 2;
                float* dd = acc[i][j];
                *(float2*)&out[((size_t)b * CIN + c) * NPIX + m] =
                    make_float2(dd[0] * scale + b0, dd[1] * scale + b0);
                *(float2*)&out[((size_t)b * CIN + c + 8) * NPIX + m] =
                    make_float2(dd[2] * scale + b1, dd[3] * scale + b1);
            }
        }
    }
}

// ------------------------------- launch -------------------------------------
extern "C" void kernel_launch(void* const* d_in, const int* in_sizes, int n_in,
                              void* d_out, int out_size) {
    const float* x  = (const float*)d_in[0];
    const float* wq = (const float*)d_in[1];
    const float* bq = (const float*)d_in[2];
    const float* wk = (const float*)d_in[3];
    const float* bk = (const float*)d_in[4];
    const float* wv = (const float*)d_in[5];
    const float* bv = (const float*)d_in[6];
    const float* wg = (const float*)d_in[7];
    const float* bg = (const float*)d_in[8];
    float* out = (float*)d_out;

    float *w2p, *bcp;
    __half *wcp, *qp, *kp, *vp;
    cudaGetSymbolAddress((void**)&w2p, g_w2);
    cudaGetSymbolAddress((void**)&wcp, g_wc);
    cudaGetSymbolAddress((void**)&bcp, g_bc);
    cudaGetSymbolAddress((void**)&qp, g_q);
    cudaGetSymbolAddress((void**)&kp, g_k);
    cudaGetSymbolAddress((void**)&vp, g_v);

    const int F_SMEM = TOT_H * (int)sizeof(__half);  // 181248
    cudaFuncSetAttribute(fused_attn, cudaFuncAttributeMaxDynamicSharedMemorySize, F_SMEM);

    fold_w<<<CIN, CIN>>>(wg, wv, w2p);
    pack_weights<<<384, CIN>>>(wq, wk, w2p, bq, bk, wg, bv, wcp, bcp);

    proj_qkv<<<dim3(3, NPIX / 128, BATCH), 256>>>(x, wcp, bcp, qp, kp, vp);

    fused_attn<<<dim3(NPIX / 128, BATCH), 384, F_SMEM>>>(qp, kp, vp, bg, out);
}

// round 15
// speedup vs baseline: 1.0787x; 1.0104x over previous
#include <cuda_runtime.h>
#include <cuda_fp16.h>
#include <cstdint>

#define NPIX 4096
#define CIN  256
#define CQK  64
#define BATCH 4
#define NCH  (NPIX / 64)

// ------------------------- device scratch ----------------------------------
__device__ float  g_w2[CIN * CIN];
__device__ __half g_wc[384 * CIN];
__device__ float  g_bc[384];
__device__ __half g_q[(size_t)BATCH * NPIX * CQK];   // [b][n][o]
__device__ __half g_k[(size_t)BATCH * NPIX * CQK];   // [b][m][o]
__device__ __half g_v[(size_t)BATCH * CIN * NPIX];   // [b][c][n]

// ------------------------- helpers -----------------------------------------
__device__ __forceinline__ uint32_t smem_u32(const void* p) {
    uint32_t a;
    asm("{ .reg .u64 t; cvta.to.shared.u64 t, %1; cvt.u32.u64 %0, t; }" : "=r"(a) : "l"(p));
    return a;
}
__device__ __forceinline__ void ldsm_x4(uint32_t a[4], uint32_t addr) {
    asm volatile("ldmatrix.sync.aligned.m8n8.x4.shared.b16 {%0,%1,%2,%3}, [%4];"
                 : "=r"(a[0]), "=r"(a[1]), "=r"(a[2]), "=r"(a[3]) : "r"(addr));
}
__device__ __forceinline__ void ldsm_x2(uint32_t a[2], uint32_t addr) {
    asm volatile("ldmatrix.sync.aligned.m8n8.x2.shared.b16 {%0,%1}, [%2];"
                 : "=r"(a[0]), "=r"(a[1]) : "r"(addr));
}
__device__ __forceinline__ void ldsm_x4_t(uint32_t a[4], uint32_t addr) {
    asm volatile("ldmatrix.sync.aligned.m8n8.x4.trans.shared.b16 {%0,%1,%2,%3}, [%4];"
                 : "=r"(a[0]), "=r"(a[1]), "=r"(a[2]), "=r"(a[3]) : "r"(addr));
}
__device__ __forceinline__ void ldsm_x2_t(uint32_t a[2], uint32_t addr) {
    asm volatile("ldmatrix.sync.aligned.m8n8.x2.trans.shared.b16 {%0,%1}, [%2];"
                 : "=r"(a[0]), "=r"(a[1]) : "r"(addr));
}
__device__ __forceinline__ void mma16816(float d[4], const uint32_t a[4], const uint32_t* b) {
    asm volatile(
        "mma.sync.aligned.m16n8k16.row.col.f32.f16.f16.f32 "
        "{%0,%1,%2,%3}, {%4,%5,%6,%7}, {%8,%9}, {%0,%1,%2,%3};"
        : "+f"(d[0]), "+f"(d[1]), "+f"(d[2]), "+f"(d[3])
        : "r"(a[0]), "r"(a[1]), "r"(a[2]), "r"(a[3]), "r"(b[0]), "r"(b[1]));
}
// fp16-accumulate variant: D fragment = 2 b32 regs of packed half2
__device__ __forceinline__ void mma16816_h(uint32_t d[2], const uint32_t a[4], const uint32_t* b) {
    asm volatile(
        "mma.sync.aligned.m16n8k16.row.col.f16.f16.f16.f16 "
        "{%0,%1}, {%2,%3,%4,%5}, {%6,%7}, {%0,%1};"
        : "+r"(d[0]), "+r"(d[1])
        : "r"(a[0]), "r"(a[1]), "r"(a[2]), "r"(a[3]), "r"(b[0]), "r"(b[1]));
}
#define CP_ASYNC16(dst, src) \
    asm volatile("cp.async.cg.shared.global [%0], [%1], 16;" :: "r"(dst), "l"(src))
#define CP_COMMIT() asm volatile("cp.async.commit_group;" ::: "memory")
#define CP_WAIT(n)  asm volatile("cp.async.wait_group %0;" :: "n"(n) : "memory")
#define BAR_SYNC(id, cnt)   asm volatile("bar.sync %0, %1;" :: "r"(id), "r"(cnt) : "memory")
#define BAR_ARRIVE(id, cnt) asm volatile("bar.arrive %0, %1;" :: "r"(id), "r"(cnt) : "memory")
#define MEMBAR_CTA() asm volatile("membar.cta;" ::: "memory")

// named barrier ids (0 reserved for __syncthreads)
#define FULL_BAR(p)  (1 + (p))   // energy arrives(128), AV syncs(256); count 384
#define EMPTY_BAR(p) (3 + (p))   // AV arrives(256), energy syncs(128); count 384
#define EN_BAR 5                 // energy-group local (used only at en==1), count 128

__device__ __forceinline__ unsigned pk2(float a, float b) {
    __half2 h = __floats2half2_rn(a, b);
    return *(unsigned*)&h;
}
// elu on an already-packed half2: x>0 ? x : exp(x)-1
__device__ __forceinline__ unsigned elu2h(unsigned hu) {
    __half2 h = *(__half2*)&hu;
    __half2 hl = __hmul2(h, __float2half2_rn(1.44269504f));
    unsigned eu;
    asm("ex2.approx.f16x2 %0, %1;" : "=r"(eu) : "r"(*(unsigned*)&hl));
    __half2 em1 = __hsub2(*(__half2*)&eu, __float2half2_rn(1.0f));
    __half2 mask = __hgt2(h, __float2half2_rn(0.0f));
    __half2 r = __hfma2(mask, __hsub2(h, em1), em1);
    return *(unsigned*)&r;
}

// ------------------------- weight folding / packing ------------------------
__global__ void fold_w(const float* __restrict__ wg, const float* __restrict__ wv,
                       float* __restrict__ w2) {
    int o = blockIdx.x, j = threadIdx.x;
    float s = 0.f;
    for (int c = 0; c < CIN; c++) s += wg[o * CIN + c] * wv[c * CIN + j];
    w2[o * CIN + j] = s;
}
__global__ void pack_weights(const float* __restrict__ wq, const float* __restrict__ wk,
                             const float* __restrict__ w2, const float* __restrict__ bq,
                             const float* __restrict__ bk, const float* __restrict__ wg,
                             const float* __restrict__ bv, __half* __restrict__ Wc,
                             float* __restrict__ bc) {
    int r = blockIdx.x, c = threadIdx.x;
    const float* src = r < 64 ? wq + r * CIN : (r < 128 ? wk + (r - 64) * CIN : w2 + (r - 128) * CIN);
    Wc[r * CIN + c] = __float2half(src[c]);
    if (c == 0) {
        if (r < 64) bc[r] = bq[r];
        else if (r < 128) bc[r] = bk[r - 64];
        else {
            float s = 0.f;
            int o = r - 128;
            for (int cc = 0; cc < CIN; cc++) s += wg[o * CIN + cc] * bv[cc];
            bc[r] = s;
        }
    }
}

// ----------------- fused QKV projection (HMMA, fp16) -----------------------
#define XST 136
#define WST 72

__global__ __launch_bounds__(256) void proj_qkv(
    const float* __restrict__ X, const __half* __restrict__ Wc,
    const float* __restrict__ bc, __half* __restrict__ qout,
    __half* __restrict__ kout, __half* __restrict__ vout) {
    __shared__ __align__(16) __half XT[64 * XST];
    __shared__ __align__(16) __half WT[128 * WST];
    const int tid = threadIdx.x, lane = tid & 31, w = tid >> 5;
    const int wtile = blockIdx.x, n0 = blockIdx.y * 128, b = blockIdx.z;
    const float* Xb = X + (size_t)b * CIN * NPIX;
    const __half* Wrow = Wc + (size_t)wtile * 128 * CIN;

    const int wa = (w >> 2) * 64, wb = (w & 3) * 32;
    const uint32_t XTb = smem_u32(XT), WTb = smem_u32(WT);
    float d[4][4][4] = {};

    for (int ck = 0; ck < 4; ck++) {
        const int c0 = ck * 64;
#pragma unroll
        for (int it = 0; it < 8; it++) {
            int idx = it * 256 + tid;
            int cc = idx >> 5, ng = idx & 31;
            float4 x4 = *(const float4*)&Xb[(size_t)(c0 + cc) * NPIX + n0 + ng * 4];
            uint2 u;
            u.x = pk2(x4.x, x4.y);
            u.y = pk2(x4.z, x4.w);
            *(uint2*)&XT[cc * XST + ng * 4] = u;
        }
#pragma unroll
        for (int it = 0; it < 4; it++) {
            int idx = it * 256 + tid;
            int r = idx >> 3, g = idx & 7;
            *(uint4*)&WT[r * WST + g * 8] = *(const uint4*)&Wrow[(size_t)r * CIN + c0 + g * 8];
        }
        __syncthreads();

        if (wtile == 0) {
#pragma unroll
            for (int kk = 0; kk < 4; kk++) {
                const int kofs = kk * 16;
                uint32_t a[4][4], bb[4][2];
#pragma unroll
                for (int i = 0; i < 4; i++) {
                    int rc = kofs + (lane & 7) + (lane >> 4) * 8;
                    int cn = wa + i * 16 + ((lane >> 3) & 1) * 8;
                    ldsm_x4_t(a[i], XTb + (rc * XST + cn) * 2);
                }
#pragma unroll
                for (int j = 0; j < 4; j++) {
                    int l = lane & 15;
                    int row = wb + j * 8 + (l & 7);
                    int col = kofs + (l >> 3) * 8;
                    ldsm_x2(bb[j], WTb + (row * WST + col) * 2);
                }
#pragma unroll
                for (int i = 0; i < 4; i++)
#pragma unroll
                    for (int j = 0; j < 4; j++) mma16816(d[i][j], a[i], bb[j]);
            }
        } else {
#pragma unroll
            for (int kk = 0; kk < 4; kk++) {
                const int kofs = kk * 16;
                uint32_t a[4][4], bb[4][2];
#pragma unroll
                for (int i = 0; i < 4; i++) {
                    int row = wa + i * 16 + (lane & 7) + ((lane >> 3) & 1) * 8;
                    int col = kofs + (lane >> 4) * 8;
                    ldsm_x4(a[i], WTb + (row * WST + col) * 2);
                }
#pragma unroll
                for (int j = 0; j < 4; j++) {
                    int l = lane & 15;
                    int rc = kofs + l;
                    int cn = wb + j * 8;
                    ldsm_x2_t(bb[j], XTb + (rc * XST + cn) * 2);
                }
#pragma unroll
                for (int i = 0; i < 4; i++)
#pragma unroll
                    for (int j = 0; j < 4; j++) mma16816(d[i][j], a[i], bb[j]);
            }
        }
        __syncthreads();
    }

    if (wtile == 0) {
#pragma unroll
        for (int j = 0; j < 4; j++) {
            int o = wb + j * 8 + (lane & 3) * 2;
            float b0 = bc[o], b1 = bc[o + 1];
            __half* dst = o < 64 ? qout : kout;
            int oo = o < 64 ? o : o - 64;
#pragma unroll
            for (int i = 0; i < 4; i++) {
                int n = n0 + wa + i * 16 + (lane >> 2);
                float* dd = d[i][j];
                *(unsigned*)&dst[((size_t)b * NPIX + n) * CQK + oo] = pk2(dd[0] + b0, dd[1] + b1);
                *(unsigned*)&dst[((size_t)b * NPIX + n + 8) * CQK + oo] = pk2(dd[2] + b0, dd[3] + b1);
            }
        }
    } else {
#pragma unroll
        for (int i = 0; i < 4; i++) {
            int c = (wtile - 1) * 128 + wa + i * 16 + (lane >> 2);
            float b0 = bc[128 + c], b1 = bc[128 + c + 8];
#pragma unroll
            for (int j = 0; j < 4; j++) {
                int n = n0 + wb + j * 8 + (lane & 3) * 2;
                float* dd = d[i][j];
                *(unsigned*)&vout[((size_t)b * CIN + c) * NPIX + n] = pk2(dd[0] + b0, dd[1] + b0);
                *(unsigned*)&vout[((size_t)b * CIN + c + 8) * NPIX + n] = pk2(dd[2] + b1, dd[3] + b1);
            }
        }
    }
}

// ------ fused attention: decoupled producer/consumer warp groups -----------
// CTA = (m-tile 128, batch), 384 thr. Warps 0-7: AV consumers (64c x 64m);
// warps 8-11: energy producers (32m x 64n, k register-resident, fp16-acc MMA).
// E double-buffered, FULL/EMPTY named barriers; minimal barrier count.
#define FST 72   // k, q stride (halves)
#define EST 72   // E stride (halves)
#define K_OFF 0                           // 128*72 = 9216
#define E_OFF(p) (9216 + (p) * 9216)      // 2 x 128*72
#define Q_OFF(i) (27648 + (i) * 4608)     // 3 x 64*72
#define V_OFF(i) (41472 + (i) * 16384)    // 3 x 256*64 (swizzled)
#define TOT_H 90624                       // halves = 181248 B

__global__ __launch_bounds__(384, 1) void fused_attn(
    const __half* __restrict__ qg, const __half* __restrict__ kg,
    const __half* __restrict__ vg, const float* __restrict__ bgb,
    float* __restrict__ out) {
    extern __shared__ __half sm[];
    const int tid = threadIdx.x, lane = tid & 31, w = tid >> 5;
    const int m0 = blockIdx.x * 128, b = blockIdx.y;
    const uint32_t smb = smem_u32(sm);

    const __half* qgb = qg + (size_t)b * NPIX * CQK;
    const __half* vgb = vg + (size_t)b * CIN * NPIX;

    auto prefetch_v = [&](int i) {  // AV threads only (tid < 256)
        if (i < NCH) {
            const int n0 = i * 64;
            const uint32_t vdst = smb + V_OFF(i % 3) * 2;
#pragma unroll
            for (int it = 0; it < 8; it++) {
                int idx = tid + 256 * it;
                int r = idx >> 3, s = idx & 7;
                CP_ASYNC16(vdst + (r * 64 + ((s ^ (r & 7)) * 8)) * 2,
                           vgb + (size_t)r * NPIX + n0 + s * 8);
            }
        }
        CP_COMMIT();
    };
    auto prefetch_q = [&](int i) {  // energy threads only (tid >= 256)
        if (i < NCH) {
            const uint32_t qdst = smb + Q_OFF(i % 3) * 2;
            int t = tid - 256;
#pragma unroll
            for (int it = 0; it < 4; it++) {
                int idx = t + 128 * it;
                int r = idx >> 3, s = idx & 7;
                CP_ASYNC16(qdst + (r * FST + s * 8) * 2,
                           qgb + (size_t)(i * 64 + r) * CQK + s * 8);
            }
        }
        CP_COMMIT();
    };

    // ---- prologue: k (AV threads) + q(0) (energy threads) direct loads
    if (tid < 256) {
        const uint4* kg4 = (const uint4*)(kg + ((size_t)b * NPIX + m0) * CQK);
#pragma unroll
        for (int it = 0; it < 4; it++) {
            int idx = tid + 256 * it;
            int r = idx >> 3, s = idx & 7;
            *(uint4*)&sm[K_OFF + r * FST + s * 8] = kg4[idx];
        }
        prefetch_v(0);
        prefetch_v(1);
    } else {
        const uint4* qg4 = (const uint4*)qgb;
        int t = tid - 256;
#pragma unroll
        for (int it = 0; it < 4; it++) {
            int idx = t + 128 * it;
            int r = idx >> 3, s = idx & 7;
            *(uint4*)&sm[Q_OFF(0) + r * FST + s * 8] = qg4[idx];
        }
        prefetch_q(1);
        prefetch_q(2);
    }
    __syncthreads();  // k, q(0) visible to everyone

    const uint32_t ksb = smb + K_OFF * 2;

    if (w >= 8) {
        // =================== ENERGY PRODUCERS (4 warps), fp16-acc ==========
        const int ew = w - 8;
        const int wme = ew * 32;

        uint32_t kfr[4][2][4];
#pragma unroll
        for (int kk = 0; kk < 4; kk++)
#pragma unroll
            for (int i = 0; i < 2; i++) {
                int row = wme + i * 16 + (lane & 7) + ((lane >> 3) & 1) * 8;
                int col = kk * 16 + (lane >> 4) * 8;
                ldsm_x4(kfr[kk][i], ksb + (row * FST + col) * 2);
            }

        auto energy = [&](int en) {
            const uint32_t qsb = smb + Q_OFF(en % 3) * 2;
            const uint32_t edst = smb + E_OFF(en & 1) * 2;
            uint32_t de[2][8][2] = {};  // packed half2 accumulators
#pragma unroll
            for (int kk = 0; kk < 4; kk++) {
                const int ko = kk * 16;
#pragma unroll
                for (int jj = 0; jj < 4; jj++) {
                    uint32_t b4[4];
                    int row = jj * 16 + (lane & 7) + (lane >> 4) * 8;
                    int col = ko + ((lane >> 3) & 1) * 8;
                    ldsm_x4(b4, qsb + (row * FST + col) * 2);
#pragma unroll
                    for (int i = 0; i < 2; i++) {
                        mma16816_h(de[i][2 * jj], kfr[kk][i], b4);
                        mma16816_h(de[i][2 * jj + 1], kfr[kk][i], b4 + 2);
                    }
                }
            }
            const int m = wme + (lane >> 2);
            const int nb = (lane & 3) * 2;
#pragma unroll
            for (int i = 0; i < 2; i++)
#pragma unroll
                for (int j = 0; j < 8; j++) {
                    int col = nb + j * 8;
                    asm volatile("st.shared.u32 [%0], %1;" ::
                                 "r"(edst + ((m + i * 16) * EST + col) * 2),
                                 "r"(elu2h(de[i][j][0])));
                    asm volatile("st.shared.u32 [%0], %1;" ::
                                 "r"(edst + ((m + i * 16 + 8) * EST + col) * 2),
                                 "r"(elu2h(de[i][j][1])));
                }
        };

        energy(0);
        MEMBAR_CTA();
        BAR_ARRIVE(FULL_BAR(0), 384);

        for (int en = 1; en < NCH; en++) {
            CP_WAIT(1);                                 // q(en) group complete
            if (en >= 2) BAR_SYNC(EMPTY_BAR(en & 1), 384);  // also q-visibility sync
            else BAR_SYNC(EN_BAR, 128);                 // en==1: group-local visibility
            prefetch_q(en + 2);
            energy(en);
            MEMBAR_CTA();
            BAR_ARRIVE(FULL_BAR(en & 1), 384);
        }
    } else {
        // =================== AV CONSUMERS (8 warps), fp32 acc ==============
        const int wc = (w >> 1) * 64, wm = (w & 1) * 64;
        float acc[4][8][4] = {};

        for (int ch = 0; ch < NCH; ch++) {
            CP_WAIT(1);                        // v(ch) group complete
            BAR_SYNC(FULL_BAR(ch & 1), 384);   // E[ch&1] produced + v visibility
            prefetch_v(ch + 2);                // safe: all AV past ch-1

            const uint32_t vsb = smb + V_OFF(ch % 3) * 2;
            const uint32_t esb = smb + E_OFF(ch & 1) * 2;
#pragma unroll
            for (int kk = 0; kk < 4; kk++) {
                const int ko = kk * 16;
                uint32_t a[4][4];
#pragma unroll
                for (int i = 0; i < 4; i++) {
                    int row = wc + i * 16 + (lane & 7) + ((lane >> 3) & 1) * 8;
                    int cnk = (ko >> 3) + (lane >> 4);
                    ldsm_x4(a[i], vsb + (row * 64 + ((cnk ^ (row & 7)) * 8)) * 2);
                }
#pragma unroll
                for (int jj = 0; jj < 4; jj++) {
                    uint32_t b4[4];
                    int row = wm + jj * 16 + (lane & 7) + (lane >> 4) * 8;
                    int col = ko + ((lane >> 3) & 1) * 8;
                    ldsm_x4(b4, esb + (row * EST + col) * 2);
#pragma unroll
                    for (int i = 0; i < 4; i++) {
                        mma16816(acc[i][2 * jj], a[i], b4);
                        mma16816(acc[i][2 * jj + 1], a[i], b4 + 2);
                    }
                }
            }
            BAR_ARRIVE(EMPTY_BAR(ch & 1), 384);
        }

        // ---- epilogue: /N + bias (AV warps only)
        const float scale = 1.0f / (float)NPIX;
#pragma unroll
        for (int i = 0; i < 4; i++) {
            int c = wc + i * 16 + (lane >> 2);
            float b0 = bgb[c], b1 = bgb[c + 8];
#pragma unroll
            for (int j = 0; j < 8; j++) {
                int m = m0 + wm + j * 8 + (lane & 3) * 2;
                float* dd = acc[i][j];
                *(float2*)&out[((size_t)b * CIN + c) * NPIX + m] =
                    make_float2(dd[0] * scale + b0, dd[1] * scale + b0);
                *(float2*)&out[((size_t)b * CIN + c + 8) * NPIX + m] =
                    make_float2(dd[2] * scale + b1, dd[3] * scale + b1);
            }
        }
    }
}

// ------------------------------- launch -------------------------------------
extern "C" void kernel_launch(void* const* d_in, const int* in_sizes, int n_in,
                              void* d_out, int out_size) {
    const float* x  = (const float*)d_in[0];
    const float* wq = (const float*)d_in[1];
    const float* bq = (const float*)d_in[2];
    const float* wk = (const float*)d_in[3];
    const float* bk = (const float*)d_in[4];
    const float* wv = (const float*)d_in[5];
    const float* bv = (const float*)d_in[6];
    const float* wg = (const float*)d_in[7];
    const float* bg = (const float*)d_in[8];
    float* out = (float*)d_out;

    float *w2p, *bcp;
    __half *wcp, *qp, *kp, *vp;
    cudaGetSymbolAddress((void**)&w2p, g_w2);
    cudaGetSymbolAddress((void**)&wcp, g_wc);
    cudaGetSymbolAddress((void**)&bcp, g_bc);
    cudaGetSymbolAddress((void**)&qp, g_q);
    cudaGetSymbolAddress((void**)&kp, g_k);
    cudaGetSymbolAddress((void**)&vp, g_v);

    const int F_SMEM = TOT_H * (int)sizeof(__half);  // 181248
    cudaFuncSetAttribute(fused_attn, cudaFuncAttributeMaxDynamicSharedMemorySize, F_SMEM);

    fold_w<<<CIN, CIN>>>(wg, wv, w2p);
    pack_weights<<<384, CIN>>>(wq, wk, w2p, bq, bk, wg, bv, wcp, bcp);

    proj_qkv<<<dim3(3, NPIX / 128, BATCH), 256>>>(x, wcp, bcp, qp, kp, vp);

    fused_attn<<<dim3(NPIX / 128, BATCH), 384, F_SMEM>>>(qp, kp, vp, bg, out);
}